// round 10
// baseline (speedup 1.0000x reference)
#include <cuda_runtime.h>
#include <cuda_fp16.h>
#include <cstdint>

// CausalConv1d as grouped GEMM on mma.sync fp16 single-pass.
// B=4, L=4096, D=2048, K=4, G=8.
// Per (b,g): C[4096,256] = A[4096,1024] x B[1024,256],
//   A[l, (ks,cin)] = x[b, l+ks-3, g*256+cin] (causal), B[(ks,cin), n] = w[ks, cin, g*256+n].
// R7: 213.5us fp16 single-pass. R9: profiled main kernel: 175.8us, tensor=64.6%
//   (HMMA ~7.2cyc/SMSP legacy path -> 113us ceiling), L1=65%, regs=128 (2 CTA/SM exactly).
// R10: ONE register-neutral change: per-warp tap stagger to desync LDSM/MMA phases
//   across SMSP-mates (taps are accumulation-order independent).

#define B_ 4
#define L_ 4096
#define D_ 2048
#define CPG 256
#define TM 128
#define TN 128
#define NSTAGES 16     // 4 channel blocks x 4 taps
#define NTHREADS 256

// __device__ scratch: pre-converted fp16 copies of x and w.
__device__ __half g_x16[B_ * L_ * D_];
__device__ __half g_w16[4 * 256 * D_];

#define NX4 (B_ * L_ * D_ / 4)        // 8388608 float4 units in x
#define NW4 (4 * 256 * D_ / 4)        // 524288 float4 units in w

// smem layout (bytes):
//  A: 2 bufs x [132 rows][128B]  (rows 131 used: l0-3 .. l0+127; 64ch x fp16)
//  B: 3 bufs x [64 rows][256B]   (128 n x fp16)
#define A_BUF 16896         // 132*128
#define OFF_B 33792         // 2*A_BUF
#define B_BUF 16384         // 64*256
#define SMEM_TOTAL (OFF_B + 3 * B_BUF)   // 82944 -> still 2 CTAs/SM

__device__ __forceinline__ uint32_t s2u(const void* p) {
    uint32_t a;
    asm("{ .reg .u64 t; cvta.to.shared.u64 t, %1; cvt.u32.u64 %0, t; }" : "=r"(a) : "l"(p));
    return a;
}

__device__ __forceinline__ void cp16(uint32_t dst, const void* src, uint32_t bytes) {
    asm volatile("cp.async.cg.shared.global [%0], [%1], 16, %2;"
                 :: "r"(dst), "l"(src), "r"(bytes));
}

#define LDSM4(r0, r1, r2, r3, a)                                                   \
    asm volatile("ldmatrix.sync.aligned.m8n8.x4.shared.b16 {%0,%1,%2,%3}, [%4];"   \
                 : "=r"(r0), "=r"(r1), "=r"(r2), "=r"(r3) : "r"(a))

#define LDSM4T(r0, r1, r2, r3, a)                                                       \
    asm volatile("ldmatrix.sync.aligned.m8n8.x4.trans.shared.b16 {%0,%1,%2,%3}, [%4];"  \
                 : "=r"(r0), "=r"(r1), "=r"(r2), "=r"(r3) : "r"(a))

#define MMA(d, a0, a1, a2, a3, b0, b1)                                             \
    asm volatile("mma.sync.aligned.m16n8k16.row.col.f32.f16.f16.f32 "              \
                 "{%0,%1,%2,%3},{%4,%5,%6,%7},{%8,%9},{%0,%1,%2,%3};"              \
                 : "+f"((d)[0]), "+f"((d)[1]), "+f"((d)[2]), "+f"((d)[3])          \
                 : "r"(a0), "r"(a1), "r"(a2), "r"(a3), "r"(b0), "r"(b1))

// Fused fp32 -> fp16 conversion for x and w (one launch).
__global__ void __launch_bounds__(256) cvt_kernel(const float* __restrict__ x,
                                                  const float* __restrict__ w) {
    size_t i = (size_t)blockIdx.x * 256 + threadIdx.x;
    const float4* src;
    uint2* dst;
    size_t j;
    if (i < NX4) { src = reinterpret_cast<const float4*>(x); dst = reinterpret_cast<uint2*>(g_x16); j = i; }
    else if (i < NX4 + NW4) { src = reinterpret_cast<const float4*>(w); dst = reinterpret_cast<uint2*>(g_w16); j = i - NX4; }
    else return;
    float4 v = src[j];
    __half2 h0 = __floats2half2_rn(v.x, v.y);
    __half2 h1 = __floats2half2_rn(v.z, v.w);
    dst[j] = make_uint2(*reinterpret_cast<uint32_t*>(&h0), *reinterpret_cast<uint32_t*>(&h1));
}

// ---- loaders (all 256 threads) ----
// A block: 131 rows (l0-3 .. l0+127) x 64 ch fp16. chunks: 131*8 = 1048.
__device__ __forceinline__ void load_A(uint32_t smem_base, int abuf, int b, int l0,
                                       int gch0 /* gcol + cbase */) {
    const uint32_t base = smem_base + abuf * A_BUF;
    for (int idx = threadIdx.x; idx < 1048; idx += NTHREADS) {
        int row = idx >> 3;
        int c   = idx & 7;
        int l   = l0 - 3 + row;
        uint32_t bytes = (l >= 0) ? 16u : 0u;   // src-size 0 -> zero-fill (causal pad)
        int lc = l >= 0 ? l : 0;
        const __half* src = g_x16 + ((size_t)(b * L_ + lc) * D_ + gch0 + c * 8);
        uint32_t dst = base + row * 128 + (((uint32_t)c ^ (row & 7)) << 4);
        cp16(dst, src, bytes);
    }
}

// B stage: 64 k-rows (cin) x 128 n fp16. chunks: 64*16 = 1024.
__device__ __forceinline__ void load_B(uint32_t smem_base, int bbuf, int ks, int cbase,
                                       int ncol0 /* gcol + nt*128 */) {
    const uint32_t base = smem_base + OFF_B + bbuf * B_BUF;
    for (int idx = threadIdx.x; idx < 1024; idx += NTHREADS) {
        int row = idx >> 4;
        int c   = idx & 15;
        const __half* src = g_w16 + ((size_t)(ks * 256 + cbase + row) * D_ + ncol0 + c * 8);
        uint32_t dst = base + row * 256 + (((uint32_t)c ^ (row & 7)) << 4);
        cp16(dst, src, 16u);
    }
}

__global__ void __launch_bounds__(NTHREADS, 2)
cc1d_mma_kernel(float* __restrict__ out) {
    extern __shared__ char smem[];
    const uint32_t smem_base = s2u(smem);
    const int tid = threadIdx.x;
    const int wid = tid >> 5;
    const int lid = tid & 31;
    const int wm = wid & 3;      // warp row: 32 rows
    const int wn = wid >> 2;     // warp col: 64 cols
    // Tap stagger: wid 0..7 -> tstart 0,1,0,1,2,3,2,3. SMSP-mates (wid, wid+4)
    // differ by 2 taps -> their LDSM and MMA phases interleave on the SMSP.
    const int tstart = ((wid >> 2) << 1) | (wid & 1);

    const int bid = blockIdx.x;
    const int nt = bid & 1;
    const int lt = (bid >> 1) & 31;
    const int g  = (bid >> 6) & 7;
    const int b  = bid >> 9;
    const int l0 = lt * TM;
    const int gcol = g * CPG;
    const int ncol0 = gcol + nt * TN;

    // ---- prologue: G0={A0,B0}, G1={B1} ----
    load_A(smem_base, 0, b, l0, gcol + 0);
    load_B(smem_base, 0, /*ks=*/0, /*cbase=*/0, ncol0);
    asm volatile("cp.async.commit_group;");
    load_B(smem_base, 1, /*ks=*/1, /*cbase=*/0, ncol0);
    asm volatile("cp.async.commit_group;");

    float acc[2][8][4];
#pragma unroll
    for (int u = 0; u < 2; ++u)
#pragma unroll
        for (int j = 0; j < 8; ++j)
#pragma unroll
            for (int q = 0; q < 4; ++q) acc[u][j][q] = 0.f;

    for (int s = 0; s < NSTAGES; ++s) {
        const int ks = s & 3;
        const uint32_t sA = smem_base + ((s >> 2) & 1) * A_BUF;
        const uint32_t sB = smem_base + OFF_B + (s % 3) * B_BUF;

        if (s == NSTAGES - 1) asm volatile("cp.async.wait_group 0;");
        else                  asm volatile("cp.async.wait_group 1;");
        __syncthreads();

        // Issue loads for stage s+2 right away (buffers free since stage s-1).
        if (s < NSTAGES - 2) {
            const int s2 = s + 2;
            if ((s2 & 3) == 0)
                load_A(smem_base, (s2 >> 2) & 1, b, l0, gcol + (s2 >> 2) * 64);
            load_B(smem_base, s2 % 3, s2 & 3, (s2 >> 2) * 64, ncol0);
            asm volatile("cp.async.commit_group;");
        }

#pragma unroll
        for (int i = 0; i < 4; ++i) {
            const int t = (i + tstart) & 3;   // per-warp tap order (accum-order free)
            uint32_t ah[2][4];
#pragma unroll
            for (int u = 0; u < 2; ++u) {
                int row = wm * 32 + u * 16 + (lid & 15) + ks;
                int lc  = t * 2 + (lid >> 4);
                uint32_t addr = sA + row * 128 + (((uint32_t)lc ^ (row & 7)) << 4);
                LDSM4(ah[u][0], ah[u][1], ah[u][2], ah[u][3], addr);
            }
            uint32_t bh[4][4];
#pragma unroll
            for (int j2 = 0; j2 < 4; ++j2) {
                int row = t * 16 + (lid & 15);
                int lc  = wn * 8 + j2 * 2 + (lid >> 4);
                uint32_t addr = sB + row * 256 + (((uint32_t)lc ^ (row & 7)) << 4);
                LDSM4T(bh[j2][0], bh[j2][1], bh[j2][2], bh[j2][3], addr);
            }
#pragma unroll
            for (int u = 0; u < 2; ++u)
#pragma unroll
                for (int j = 0; j < 8; ++j) {
                    int j2 = j >> 1, o = (j & 1) * 2;
                    MMA(acc[u][j], ah[u][0], ah[u][1], ah[u][2], ah[u][3],
                        bh[j2][o], bh[j2][o + 1]);
                }
        }
    }

    // ---- epilogue: acc regs -> out ----
#pragma unroll
    for (int u = 0; u < 2; ++u)
#pragma unroll
        for (int j = 0; j < 8; ++j) {
            int m0 = wm * 32 + u * 16 + (lid >> 2);
            int n  = wn * 64 + j * 8 + (lid & 3) * 2;
            float* p = out + (size_t)(b * L_ + l0 + m0) * D_ + ncol0 + n;
            *reinterpret_cast<float2*>(p) = make_float2(acc[u][j][0], acc[u][j][1]);
            *reinterpret_cast<float2*>(p + 8 * D_) = make_float2(acc[u][j][2], acc[u][j][3]);
        }
}

extern "C" void kernel_launch(void* const* d_in, const int* in_sizes, int n_in,
                              void* d_out, int out_size) {
    const float* x = (const float*)d_in[0];   // [4, 4096, 2048] fp32
    const float* w = (const float*)d_in[1];   // [4, 256, 2048] fp32
    float* out = (float*)d_out;               // [4, 4096, 2048] fp32

    // pre-convert fp32 -> fp16 (fused, one launch)
    cvt_kernel<<<(NX4 + NW4 + 255) / 256, 256>>>(x, w);

    cudaFuncSetAttribute(cc1d_mma_kernel, cudaFuncAttributeMaxDynamicSharedMemorySize, SMEM_TOTAL);
    // 2048 CTAs = 4 b x 8 g x 32 l-tiles x 2 n-tiles
    cc1d_mma_kernel<<<B_ * 8 * 32 * 2, NTHREADS, SMEM_TOTAL>>>(out);
}

// round 11
// speedup vs baseline: 1.1629x; 1.1629x over previous
#include <cuda_runtime.h>
#include <cuda_fp16.h>
#include <cstdint>

// CausalConv1d as grouped GEMM on mma.sync fp16 single-pass.
// B=4, L=4096, D=2048, K=4, G=8.
// Per (b,g): C[4096,256] = A[4096,1024] x B[1024,256],
//   A[l, (ks,cin)] = x[b, l+ks-3, g*256+cin] (causal), B[(ks,cin), n] = w[ks, cin, g*256+n].
// R7/R9: 213.5us. Main kernel 176us: tensor 64.6% (~7.2cyc/HMMA) + L1 63% co-saturated;
// cvt_x kernel 32us fully serialized while main kernel DRAM=11%.
// R10: tap stagger FAILED (222us) -> reverted.
// R11: eliminate g_x16: cp.async fp32 A tile per CTA (linear smem), convert smem->smem
//   fp32->fp16 at block boundaries (4x per CTA). Saves ~30us of serialized cvt.

#define B_ 4
#define L_ 4096
#define D_ 2048
#define CPG 256
#define TM 128
#define TN 128
#define NSTAGES 16     // 4 channel blocks x 4 taps
#define NTHREADS 256

// __device__ scratch: pre-converted fp16 copy of w only (x converted in-kernel).
__device__ __half g_w16[4 * 256 * D_];
#define NW4 (4 * 256 * D_ / 4)        // 524288 float4 units in w

// smem layout (bytes):
//  A32: 1 buf [131 rows][256B] fp32, linear           @ 0      (33536)
//  A16: 1 buf [132 rows][128B] fp16, swizzled         @ 33536  (16896)
//  B:   3 bufs [64 rows][256B] fp16, swizzled         @ 50432  (3*16384)
#define OFF_A32 0
#define A32_BYTES 33536
#define OFF_A16 33536
#define OFF_B 50432
#define B_BUF 16384
#define SMEM_TOTAL (OFF_B + 3 * B_BUF)   // 99584 -> 2 CTAs/SM

__device__ __forceinline__ uint32_t s2u(const void* p) {
    uint32_t a;
    asm("{ .reg .u64 t; cvta.to.shared.u64 t, %1; cvt.u32.u64 %0, t; }" : "=r"(a) : "l"(p));
    return a;
}

__device__ __forceinline__ void cp16(uint32_t dst, const void* src, uint32_t bytes) {
    asm volatile("cp.async.cg.shared.global [%0], [%1], 16, %2;"
                 :: "r"(dst), "l"(src), "r"(bytes));
}

#define LDSM4(r0, r1, r2, r3, a)                                                   \
    asm volatile("ldmatrix.sync.aligned.m8n8.x4.shared.b16 {%0,%1,%2,%3}, [%4];"   \
                 : "=r"(r0), "=r"(r1), "=r"(r2), "=r"(r3) : "r"(a))

#define LDSM4T(r0, r1, r2, r3, a)                                                       \
    asm volatile("ldmatrix.sync.aligned.m8n8.x4.trans.shared.b16 {%0,%1,%2,%3}, [%4];"  \
                 : "=r"(r0), "=r"(r1), "=r"(r2), "=r"(r3) : "r"(a))

#define MMA(d, a0, a1, a2, a3, b0, b1)                                             \
    asm volatile("mma.sync.aligned.m16n8k16.row.col.f32.f16.f16.f32 "              \
                 "{%0,%1,%2,%3},{%4,%5,%6,%7},{%8,%9},{%0,%1,%2,%3};"              \
                 : "+f"((d)[0]), "+f"((d)[1]), "+f"((d)[2]), "+f"((d)[3])          \
                 : "r"(a0), "r"(a1), "r"(a2), "r"(a3), "r"(b0), "r"(b1))

// fp32 -> fp16 conversion for w only (12 MB total, ~2us).
__global__ void __launch_bounds__(256) cvt_w_kernel(const float* __restrict__ w) {
    size_t i = (size_t)blockIdx.x * 256 + threadIdx.x;
    float4 v = reinterpret_cast<const float4*>(w)[i];
    __half2 h0 = __floats2half2_rn(v.x, v.y);
    __half2 h1 = __floats2half2_rn(v.z, v.w);
    reinterpret_cast<uint2*>(g_w16)[i] =
        make_uint2(*reinterpret_cast<uint32_t*>(&h0), *reinterpret_cast<uint32_t*>(&h1));
}

// ---- loaders (all 256 threads) ----
// A32 block: 131 rows (l0-3 .. l0+127) x 64 ch fp32, linear. chunks: 131*16 = 2096.
__device__ __forceinline__ void load_A32(uint32_t smem_base, const float* __restrict__ x,
                                         int b, int l0, int gch0) {
    const uint32_t base = smem_base + OFF_A32;
    for (int idx = threadIdx.x; idx < 2096; idx += NTHREADS) {
        int row = idx >> 4;
        int c4  = idx & 15;          // float4 unit along channels
        int l   = l0 - 3 + row;
        uint32_t bytes = (l >= 0) ? 16u : 0u;   // src-size 0 -> zero-fill (causal pad)
        int lc = l >= 0 ? l : 0;
        const float* src = x + ((size_t)(b * L_ + lc) * D_ + gch0 + c4 * 4);
        cp16(base + row * 256 + c4 * 16, src, bytes);
    }
}

// Convert A32 (linear fp32) -> A16 (swizzled fp16). Behind barriers at block boundary.
__device__ __forceinline__ void convert_A(char* smem) {
    const char* a32 = smem + OFF_A32;
    char* a16 = smem + OFF_A16;
    for (int idx = threadIdx.x; idx < 2096; idx += NTHREADS) {
        int row = idx >> 4;
        int c4  = idx & 15;
        float4 v = *reinterpret_cast<const float4*>(a32 + row * 256 + c4 * 16);
        __half2 h0 = __floats2half2_rn(v.x, v.y);
        __half2 h1 = __floats2half2_rn(v.z, v.w);
        // 16B-chunk index in fp16 row = c4>>1; low/high 8B half = c4&1.
        uint32_t dst = row * 128 + ((((uint32_t)c4 >> 1) ^ (row & 7)) << 4) + (c4 & 1) * 8;
        *reinterpret_cast<uint2*>(a16 + dst) =
            make_uint2(*reinterpret_cast<uint32_t*>(&h0), *reinterpret_cast<uint32_t*>(&h1));
    }
}

// B stage: 64 k-rows (cin) x 128 n fp16. chunks: 64*16 = 1024.
__device__ __forceinline__ void load_B(uint32_t smem_base, int bbuf, int ks, int cbase,
                                       int ncol0 /* gcol + nt*128 */) {
    const uint32_t base = smem_base + OFF_B + bbuf * B_BUF;
    for (int idx = threadIdx.x; idx < 1024; idx += NTHREADS) {
        int row = idx >> 4;
        int c   = idx & 15;
        const __half* src = g_w16 + ((size_t)(ks * 256 + cbase + row) * D_ + ncol0 + c * 8);
        uint32_t dst = base + row * 256 + (((uint32_t)c ^ (row & 7)) << 4);
        cp16(dst, src, 16u);
    }
}

__global__ void __launch_bounds__(NTHREADS, 2)
cc1d_mma_kernel(const float* __restrict__ x, float* __restrict__ out) {
    extern __shared__ char smem[];
    const uint32_t smem_base = s2u(smem);
    const int tid = threadIdx.x;
    const int wid = tid >> 5;
    const int lid = tid & 31;
    const int wm = wid & 3;      // warp row: 32 rows
    const int wn = wid >> 2;     // warp col: 64 cols

    const int bid = blockIdx.x;
    const int nt = bid & 1;
    const int lt = (bid >> 1) & 31;
    const int g  = (bid >> 6) & 7;
    const int b  = bid >> 9;
    const int l0 = lt * TM;
    const int gcol = g * CPG;
    const int ncol0 = gcol + nt * TN;

    // ---- prologue: G0={A32 block0, B0}, G1={B1} ----
    load_A32(smem_base, x, b, l0, gcol + 0);
    load_B(smem_base, 0, /*ks=*/0, /*cbase=*/0, ncol0);
    asm volatile("cp.async.commit_group;");
    load_B(smem_base, 1, /*ks=*/1, /*cbase=*/0, ncol0);
    asm volatile("cp.async.commit_group;");

    float acc[2][8][4];
#pragma unroll
    for (int u = 0; u < 2; ++u)
#pragma unroll
        for (int j = 0; j < 8; ++j)
#pragma unroll
            for (int q = 0; q < 4; ++q) acc[u][j][q] = 0.f;

    const uint32_t sA = smem_base + OFF_A16;   // single A16 buffer

    for (int s = 0; s < NSTAGES; ++s) {
        const int ks = s & 3;
        const uint32_t sB = smem_base + OFF_B + (s % 3) * B_BUF;

        if (s == NSTAGES - 1) asm volatile("cp.async.wait_group 0;");
        else                  asm volatile("cp.async.wait_group 1;");
        __syncthreads();

        // Block boundary: A32(block s/4) complete (committed >=2 groups ago);
        // previous block's A16 fully consumed (barrier above). Convert in place.
        if ((s & 3) == 0) {
            convert_A(smem);
            __syncthreads();
        }

        // Issue loads for stage s+2 (B buffer (s+2)%3 free since stage s-1;
        // A32 buffer free once this block's conversion above has run).
        if (s < NSTAGES - 2) {
            const int s2 = s + 2;
            if ((s2 & 3) == 0)
                load_A32(smem_base, x, b, l0, gcol + (s2 >> 2) * 64);
            load_B(smem_base, s2 % 3, s2 & 3, (s2 >> 2) * 64, ncol0);
            asm volatile("cp.async.commit_group;");
        }

#pragma unroll
        for (int t = 0; t < 4; ++t) {
            uint32_t ah[2][4];
#pragma unroll
            for (int u = 0; u < 2; ++u) {
                int row = wm * 32 + u * 16 + (lid & 15) + ks;
                int lc  = t * 2 + (lid >> 4);
                uint32_t addr = sA + row * 128 + (((uint32_t)lc ^ (row & 7)) << 4);
                LDSM4(ah[u][0], ah[u][1], ah[u][2], ah[u][3], addr);
            }
            uint32_t bh[4][4];
#pragma unroll
            for (int j2 = 0; j2 < 4; ++j2) {
                int row = t * 16 + (lid & 15);
                int lc  = wn * 8 + j2 * 2 + (lid >> 4);
                uint32_t addr = sB + row * 256 + (((uint32_t)lc ^ (row & 7)) << 4);
                LDSM4T(bh[j2][0], bh[j2][1], bh[j2][2], bh[j2][3], addr);
            }
#pragma unroll
            for (int u = 0; u < 2; ++u)
#pragma unroll
                for (int j = 0; j < 8; ++j) {
                    int j2 = j >> 1, o = (j & 1) * 2;
                    MMA(acc[u][j], ah[u][0], ah[u][1], ah[u][2], ah[u][3],
                        bh[j2][o], bh[j2][o + 1]);
                }
        }
    }

    // ---- epilogue: acc regs -> out ----
#pragma unroll
    for (int u = 0; u < 2; ++u)
#pragma unroll
        for (int j = 0; j < 8; ++j) {
            int m0 = wm * 32 + u * 16 + (lid >> 2);
            int n  = wn * 64 + j * 8 + (lid & 3) * 2;
            float* p = out + (size_t)(b * L_ + l0 + m0) * D_ + ncol0 + n;
            *reinterpret_cast<float2*>(p) = make_float2(acc[u][j][0], acc[u][j][1]);
            *reinterpret_cast<float2*>(p + 8 * D_) = make_float2(acc[u][j][2], acc[u][j][3]);
        }
}

extern "C" void kernel_launch(void* const* d_in, const int* in_sizes, int n_in,
                              void* d_out, int out_size) {
    const float* x = (const float*)d_in[0];   // [4, 4096, 2048] fp32
    const float* w = (const float*)d_in[1];   // [4, 256, 2048] fp32
    float* out = (float*)d_out;               // [4, 4096, 2048] fp32

    // pre-convert w only (x is converted inside the main kernel)
    cvt_w_kernel<<<NW4 / 256, 256>>>(w);

    cudaFuncSetAttribute(cc1d_mma_kernel, cudaFuncAttributeMaxDynamicSharedMemorySize, SMEM_TOTAL);
    // 2048 CTAs = 4 b x 8 g x 32 l-tiles x 2 n-tiles
    cc1d_mma_kernel<<<B_ * 8 * 32 * 2, NTHREADS, SMEM_TOTAL>>>(x, out);
}

// round 12
// speedup vs baseline: 1.1672x; 1.0037x over previous
#include <cuda_runtime.h>
#include <cuda_fp16.h>
#include <cstdint>

// CausalConv1d as grouped GEMM on mma.sync fp16 single-pass.
// B=4, L=4096, D=2048, K=4, G=8.
// Per (b,g): C[4096,256] = A[4096,1024] x B[1024,256],
//   A[l, (ks,cin)] = x[b, l+ks-3, g*256+cin] (causal), B[(ks,cin), n] = w[ks, cin, g*256+n].
// R9: 213.5us (main 175.8, tensor 64.6%). R11: 191.0us -- x converted in-kernel
//   (main 187.6: convert serialized behind 2 barriers x4 blocks).
// R12: double-buffer A16, convert block k+1 DURING stage 4k+2 compute (no dedicated
//   barriers); B back to 2 bufs + post-compute barrier (measured neutral) to keep
//   smem at 100.1KB -> 2 CTAs/SM.

#define B_ 4
#define L_ 4096
#define D_ 2048
#define CPG 256
#define TM 128
#define TN 128
#define NSTAGES 16     // 4 channel blocks x 4 taps
#define NTHREADS 256

// __device__ scratch: pre-converted fp16 copy of w only (x converted in-kernel).
__device__ __half g_w16[4 * 256 * D_];
#define NW4 (4 * 256 * D_ / 4)        // 524288 float4 units in w

// smem layout (bytes):
//  A32: 1 buf [131 rows][256B] fp32, linear           @ 0      (33536)
//  A16: 2 bufs [132 rows][128B] fp16, swizzled        @ 33536  (2*16896)
//  B:   2 bufs [64 rows][256B] fp16, swizzled         @ 67328  (2*16384)
#define OFF_A32 0
#define OFF_A16 33536
#define A16_SZ 16896
#define OFF_B 67328
#define B_BUF 16384
#define SMEM_TOTAL (OFF_B + 2 * B_BUF)   // 100096 -> 2 CTAs/SM

__device__ __forceinline__ uint32_t s2u(const void* p) {
    uint32_t a;
    asm("{ .reg .u64 t; cvta.to.shared.u64 t, %1; cvt.u32.u64 %0, t; }" : "=r"(a) : "l"(p));
    return a;
}

__device__ __forceinline__ void cp16(uint32_t dst, const void* src, uint32_t bytes) {
    asm volatile("cp.async.cg.shared.global [%0], [%1], 16, %2;"
                 :: "r"(dst), "l"(src), "r"(bytes));
}

#define LDSM4(r0, r1, r2, r3, a)                                                   \
    asm volatile("ldmatrix.sync.aligned.m8n8.x4.shared.b16 {%0,%1,%2,%3}, [%4];"   \
                 : "=r"(r0), "=r"(r1), "=r"(r2), "=r"(r3) : "r"(a))

#define LDSM4T(r0, r1, r2, r3, a)                                                       \
    asm volatile("ldmatrix.sync.aligned.m8n8.x4.trans.shared.b16 {%0,%1,%2,%3}, [%4];"  \
                 : "=r"(r0), "=r"(r1), "=r"(r2), "=r"(r3) : "r"(a))

#define MMA(d, a0, a1, a2, a3, b0, b1)                                             \
    asm volatile("mma.sync.aligned.m16n8k16.row.col.f32.f16.f16.f32 "              \
                 "{%0,%1,%2,%3},{%4,%5,%6,%7},{%8,%9},{%0,%1,%2,%3};"              \
                 : "+f"((d)[0]), "+f"((d)[1]), "+f"((d)[2]), "+f"((d)[3])          \
                 : "r"(a0), "r"(a1), "r"(a2), "r"(a3), "r"(b0), "r"(b1))

// fp32 -> fp16 conversion for w only (12 MB total, ~2us).
__global__ void __launch_bounds__(256) cvt_w_kernel(const float* __restrict__ w) {
    size_t i = (size_t)blockIdx.x * 256 + threadIdx.x;
    float4 v = reinterpret_cast<const float4*>(w)[i];
    __half2 h0 = __floats2half2_rn(v.x, v.y);
    __half2 h1 = __floats2half2_rn(v.z, v.w);
    reinterpret_cast<uint2*>(g_w16)[i] =
        make_uint2(*reinterpret_cast<uint32_t*>(&h0), *reinterpret_cast<uint32_t*>(&h1));
}

// ---- loaders (all 256 threads) ----
// A32 block: 131 rows (l0-3 .. l0+127) x 64 ch fp32, linear. chunks: 131*16 = 2096.
__device__ __forceinline__ void load_A32(uint32_t smem_base, const float* __restrict__ x,
                                         int b, int l0, int gch0) {
    const uint32_t base = smem_base + OFF_A32;
    for (int idx = threadIdx.x; idx < 2096; idx += NTHREADS) {
        int row = idx >> 4;
        int c4  = idx & 15;          // float4 unit along channels
        int l   = l0 - 3 + row;
        uint32_t bytes = (l >= 0) ? 16u : 0u;   // src-size 0 -> zero-fill (causal pad)
        int lc = l >= 0 ? l : 0;
        const float* src = x + ((size_t)(b * L_ + lc) * D_ + gch0 + c4 * 4);
        cp16(base + row * 256 + c4 * 16, src, bytes);
    }
}

// Convert A32 (linear fp32) -> A16 buffer `a16buf` (swizzled fp16).
__device__ __forceinline__ void convert_A(char* smem, int a16buf) {
    const char* a32 = smem + OFF_A32;
    char* a16 = smem + OFF_A16 + a16buf * A16_SZ;
    for (int idx = threadIdx.x; idx < 2096; idx += NTHREADS) {
        int row = idx >> 4;
        int c4  = idx & 15;
        float4 v = *reinterpret_cast<const float4*>(a32 + row * 256 + c4 * 16);
        __half2 h0 = __floats2half2_rn(v.x, v.y);
        __half2 h1 = __floats2half2_rn(v.z, v.w);
        // 16B-chunk index in fp16 row = c4>>1; low/high 8B half = c4&1.
        uint32_t dst = row * 128 + ((((uint32_t)c4 >> 1) ^ (row & 7)) << 4) + (c4 & 1) * 8;
        *reinterpret_cast<uint2*>(a16 + dst) =
            make_uint2(*reinterpret_cast<uint32_t*>(&h0), *reinterpret_cast<uint32_t*>(&h1));
    }
}

// B stage: 64 k-rows (cin) x 128 n fp16. chunks: 64*16 = 1024.
__device__ __forceinline__ void load_B(uint32_t smem_base, int bbuf, int ks, int cbase,
                                       int ncol0 /* gcol + nt*128 */) {
    const uint32_t base = smem_base + OFF_B + bbuf * B_BUF;
    for (int idx = threadIdx.x; idx < 1024; idx += NTHREADS) {
        int row = idx >> 4;
        int c   = idx & 15;
        const __half* src = g_w16 + ((size_t)(ks * 256 + cbase + row) * D_ + ncol0 + c * 8);
        uint32_t dst = base + row * 256 + (((uint32_t)c ^ (row & 7)) << 4);
        cp16(dst, src, 16u);
    }
}

__global__ void __launch_bounds__(NTHREADS, 2)
cc1d_mma_kernel(const float* __restrict__ x, float* __restrict__ out) {
    extern __shared__ char smem[];
    const uint32_t smem_base = s2u(smem);
    const int tid = threadIdx.x;
    const int wid = tid >> 5;
    const int lid = tid & 31;
    const int wm = wid & 3;      // warp row: 32 rows
    const int wn = wid >> 2;     // warp col: 64 cols

    const int bid = blockIdx.x;
    const int nt = bid & 1;
    const int lt = (bid >> 1) & 31;
    const int g  = (bid >> 6) & 7;
    const int b  = bid >> 9;
    const int l0 = lt * TM;
    const int gcol = g * CPG;
    const int ncol0 = gcol + nt * TN;

    // ---- prologue: G0={A32 block0, B0}, G1={B1}; convert block0 (only serialized one) ----
    load_A32(smem_base, x, b, l0, gcol + 0);
    load_B(smem_base, 0, /*ks=*/0, /*cbase=*/0, ncol0);
    asm volatile("cp.async.commit_group;");
    load_B(smem_base, 1, /*ks=*/1, /*cbase=*/0, ncol0);
    asm volatile("cp.async.commit_group;");

    asm volatile("cp.async.wait_group 1;");   // G0 complete: A32(0), B0
    __syncthreads();
    convert_A(smem, 0);
    // Visibility of A16(0) to all warps: the stage-0 top barrier below.

    float acc[2][8][4];
#pragma unroll
    for (int u = 0; u < 2; ++u)
#pragma unroll
        for (int j = 0; j < 8; ++j)
#pragma unroll
            for (int q = 0; q < 4; ++q) acc[u][j][q] = 0.f;

    for (int s = 0; s < NSTAGES; ++s) {
        const int ks = s & 3;
        const uint32_t sA = smem_base + OFF_A16 + ((s >> 2) & 1) * A16_SZ;
        const uint32_t sB = smem_base + OFF_B + (s & 1) * B_BUF;

        if (s == NSTAGES - 1) asm volatile("cp.async.wait_group 0;");
        else                  asm volatile("cp.async.wait_group 1;");
        __syncthreads();

        // Hidden conversion: at stage 4k+2 convert block k+1 (A32(k+1) landed, covered
        // by this stage's wait; A16 buf (k+1)&1 last read at stage 4k-1). Overlaps
        // with this stage's MMAs; visibility via the 4k+3 / 4k+4 stage barriers.
        if ((s & 3) == 2 && s < 12) convert_A(smem, ((s + 2) >> 2) & 1);

#pragma unroll
        for (int t = 0; t < 4; ++t) {
            uint32_t ah[2][4];
#pragma unroll
            for (int u = 0; u < 2; ++u) {
                int row = wm * 32 + u * 16 + (lid & 15) + ks;
                int lc  = t * 2 + (lid >> 4);
                uint32_t addr = sA + row * 128 + (((uint32_t)lc ^ (row & 7)) << 4);
                LDSM4(ah[u][0], ah[u][1], ah[u][2], ah[u][3], addr);
            }
            uint32_t bh[4][4];
#pragma unroll
            for (int j2 = 0; j2 < 4; ++j2) {
                int row = t * 16 + (lid & 15);
                int lc  = wn * 8 + j2 * 2 + (lid >> 4);
                uint32_t addr = sB + row * 256 + (((uint32_t)lc ^ (row & 7)) << 4);
                LDSM4T(bh[j2][0], bh[j2][1], bh[j2][2], bh[j2][3], addr);
            }
#pragma unroll
            for (int u = 0; u < 2; ++u)
#pragma unroll
                for (int j = 0; j < 8; ++j) {
                    int j2 = j >> 1, o = (j & 1) * 2;
                    MMA(acc[u][j], ah[u][0], ah[u][1], ah[u][2], ah[u][3],
                        bh[j2][o], bh[j2][o + 1]);
                }
        }

        // Post-compute: B buffer s&1 now free for stage s+2; A32 buffer free for the
        // NEXT block load at stages 0,4,8 (its conversion ran at stage s-2).
        if (s < NSTAGES - 2) {
            __syncthreads();
            load_B(smem_base, s & 1, (s + 2) & 3, ((s + 2) >> 2) * 64, ncol0);
            if ((s & 3) == 0 && s < 12)
                load_A32(smem_base, x, b, l0, gcol + ((s >> 2) + 1) * 64);
            asm volatile("cp.async.commit_group;");
        }
    }

    // ---- epilogue: acc regs -> out ----
#pragma unroll
    for (int u = 0; u < 2; ++u)
#pragma unroll
        for (int j = 0; j < 8; ++j) {
            int m0 = wm * 32 + u * 16 + (lid >> 2);
            int n  = wn * 64 + j * 8 + (lid & 3) * 2;
            float* p = out + (size_t)(b * L_ + l0 + m0) * D_ + ncol0 + n;
            *reinterpret_cast<float2*>(p) = make_float2(acc[u][j][0], acc[u][j][1]);
            *reinterpret_cast<float2*>(p + 8 * D_) = make_float2(acc[u][j][2], acc[u][j][3]);
        }
}

extern "C" void kernel_launch(void* const* d_in, const int* in_sizes, int n_in,
                              void* d_out, int out_size) {
    const float* x = (const float*)d_in[0];   // [4, 4096, 2048] fp32
    const float* w = (const float*)d_in[1];   // [4, 256, 2048] fp32
    float* out = (float*)d_out;               // [4, 4096, 2048] fp32

    // pre-convert w only (x is converted inside the main kernel)
    cvt_w_kernel<<<NW4 / 256, 256>>>(w);

    cudaFuncSetAttribute(cc1d_mma_kernel, cudaFuncAttributeMaxDynamicSharedMemorySize, SMEM_TOTAL);
    // 2048 CTAs = 4 b x 8 g x 32 l-tiles x 2 n-tiles
    cc1d_mma_kernel<<<B_ * 8 * 32 * 2, NTHREADS, SMEM_TOTAL>>>(x, out);
}